// round 1
// baseline (speedup 1.0000x reference)
#include <cuda_runtime.h>

// GaussianWarpingScheme: out[b,c,ho,wo] = sum_{3x3 taps} exp(-8*((x-xi)^2+(y-yi)^2)) * valid * im[b,c,yi,xi]
// where x = wo - w0*(W-1)/2 style pixel coords derived from identity grid minus flow.
// Shapes: im (8,16,256,256) f32, w (8,2,256,256) f32, out (8,16,256,256) f32.

#define Bn 8
#define Cn 16
#define Hn 256
#define Wn 256
#define HWn (Hn * Wn)

__global__ void __launch_bounds__(256, 6)
gauss_warp_kernel(const float* __restrict__ im,
                  const float* __restrict__ w,
                  float* __restrict__ out)
{
    const int p = blockIdx.x * blockDim.x + threadIdx.x;   // pixel id over B*H*W
    if (p >= Bn * HWn) return;

    const int b   = p >> 16;           // / HWn (65536)
    const int rem = p & (HWn - 1);
    const int ho  = rem >> 8;          // / Wn
    const int wo  = rem & (Wn - 1);

    // flow components (coalesced)
    const float w0 = w[b * 2 * HWn + rem];
    const float w1 = w[b * 2 * HWn + HWn + rem];

    // identity grid (linspace semantics), grid = base - flow
    const float bx = -1.0f + (float)wo * (2.0f / 255.0f);
    const float by = -1.0f + (float)ho * (2.0f / 255.0f);
    const float gx = bx - w0;
    const float gy = by - w1;

    // pixel-space coords (align_corners=True)
    const float x = (gx + 1.0f) * 0.5f * 255.0f;
    const float y = (gy + 1.0f) * 0.5f * 255.0f;
    const int ix = (int)floorf(x);
    const int iy = (int)floorf(y);

    // separable gaussian weights; zero weight for out-of-range taps,
    // clamp index for the (masked) gather.
    float wx[3], wy[3];
    int   xc[3], yr[3];
#pragma unroll
    for (int j = 0; j < 3; j++) {
        const int   xi = ix + (j - 1);
        const float dx = x - (float)xi;
        const float ex = __expf(-8.0f * dx * dx);
        wx[j] = (xi >= 0 && xi < Wn) ? ex : 0.0f;
        xc[j] = min(max(xi, 0), Wn - 1);

        const int   yi = iy + (j - 1);
        const float dy = y - (float)yi;
        const float ey = __expf(-8.0f * dy * dy);
        wy[j] = (yi >= 0 && yi < Hn) ? ey : 0.0f;
        yr[j] = min(max(yi, 0), Hn - 1);
    }

    // 9 flat offsets (within one channel plane) + fused weights
    int   off[9];
    float wt[9];
#pragma unroll
    for (int i = 0; i < 3; i++)
#pragma unroll
        for (int j = 0; j < 3; j++) {
            off[i * 3 + j] = yr[i] * Wn + xc[j];
            wt[i * 3 + j]  = wy[i] * wx[j];
        }

    const float* imb  = im  + (size_t)b * Cn * HWn;
    float*       outp = out + (size_t)b * Cn * HWn + rem;

#pragma unroll
    for (int c = 0; c < Cn; c++) {
        const float* ch = imb + c * HWn;
        float acc = 0.0f;
#pragma unroll
        for (int t = 0; t < 9; t++)
            acc += wt[t] * __ldg(ch + off[t]);
        outp[c * HWn] = acc;   // coalesced store
    }
}

extern "C" void kernel_launch(void* const* d_in, const int* in_sizes, int n_in,
                              void* d_out, int out_size)
{
    // metadata order: im (8*16*256*256), w (8*2*256*256). Guard by size anyway.
    const float* im = (const float*)d_in[0];
    const float* w  = (const float*)d_in[1];
    if (n_in >= 2 && in_sizes[0] == Bn * 2 * HWn && in_sizes[1] == Bn * Cn * HWn) {
        im = (const float*)d_in[1];
        w  = (const float*)d_in[0];
    }
    float* out = (float*)d_out;

    const int total   = Bn * HWn;           // 524288 threads (one per pixel)
    const int threads = 256;
    const int blocks  = (total + threads - 1) / threads;
    gauss_warp_kernel<<<blocks, threads>>>(im, w, out);
}

// round 2
// speedup vs baseline: 2.5468x; 2.5468x over previous
#include <cuda_runtime.h>

// GaussianWarpingScheme on GB300.
// Pass 1: transpose im (B,C,H,W) -> scratch (B,H,W,C)  [channel-last]
// Pass 2: per output pixel, compute 9 separable gaussian tap weights once,
//         gather 16 channels per tap as 4 aligned float4 loads (64B/tap),
//         accumulate, store per-channel (coalesced across lanes).

#define Bn 8
#define Cn 16
#define Hn 256
#define Wn 256
#define HWn (Hn * Wn)

// 33.5 MB channel-last scratch: (B,H,W,C) as float4[.. ][4]
__device__ float4 g_imT4[(size_t)Bn * HWn * 4];

// ---------------- Pass 1: (B,C,H,W) -> (B,H,W,C) ----------------
__global__ void __launch_bounds__(256)
transpose_chw_hwc(const float* __restrict__ im)
{
    const int bh = blockIdx.x;          // 0 .. B*H-1
    const int b  = bh >> 8;
    const int h  = bh & (Hn - 1);
    const int wv = threadIdx.x;         // 0 .. 255 (x coordinate)

    const float* src = im + ((size_t)(b * Cn) * Hn + h) * Wn + wv;
    float4* dst = g_imT4 + ((size_t)((b << 8) + h) * Wn + wv) * 4;

    float v[Cn];
#pragma unroll
    for (int c = 0; c < Cn; c++)
        v[c] = src[(size_t)c * HWn];    // coalesced: consecutive lanes = consecutive w

    dst[0] = make_float4(v[0],  v[1],  v[2],  v[3]);
    dst[1] = make_float4(v[4],  v[5],  v[6],  v[7]);
    dst[2] = make_float4(v[8],  v[9],  v[10], v[11]);
    dst[3] = make_float4(v[12], v[13], v[14], v[15]);
}

// ---------------- Pass 2: gaussian gather ----------------
__global__ void __launch_bounds__(256)
gauss_warp_main(const float* __restrict__ w,
                float* __restrict__ out)
{
    const int p = blockIdx.x * blockDim.x + threadIdx.x;   // pixel id over B*H*W
    const int b   = p >> 16;
    const int rem = p & (HWn - 1);
    const int ho  = rem >> 8;
    const int wo  = rem & (Wn - 1);

    // flow components (coalesced)
    const float w0 = w[b * 2 * HWn + rem];
    const float w1 = w[b * 2 * HWn + HWn + rem];

    // identity grid (linspace semantics), grid = base - flow; pixel coords
    const float bx = -1.0f + (float)wo * (2.0f / 255.0f);
    const float by = -1.0f + (float)ho * (2.0f / 255.0f);
    const float x = ((bx - w0) + 1.0f) * 0.5f * 255.0f;
    const float y = ((by - w1) + 1.0f) * 0.5f * 255.0f;
    const int ix = (int)floorf(x);
    const int iy = (int)floorf(y);

    // separable gaussian weights; zero weight for out-of-range taps,
    // clamped index for the (masked) gather.
    float wx[3], wy[3];
    int   xc[3], yr[3];
#pragma unroll
    for (int j = 0; j < 3; j++) {
        const int   xi = ix + (j - 1);
        const float dx = x - (float)xi;
        const float ex = __expf(-8.0f * dx * dx);
        wx[j] = (xi >= 0 && xi < Wn) ? ex : 0.0f;
        xc[j] = min(max(xi, 0), Wn - 1);

        const int   yi = iy + (j - 1);
        const float dy = y - (float)yi;
        const float ey = __expf(-8.0f * dy * dy);
        wy[j] = (yi >= 0 && yi < Hn) ? ey : 0.0f;
        yr[j] = min(max(yi, 0), Hn - 1);
    }

    const float4* base = g_imT4 + (size_t)b * HWn * 4;

    float4 a0 = make_float4(0.f, 0.f, 0.f, 0.f);
    float4 a1 = a0, a2 = a0, a3 = a0;

#pragma unroll
    for (int i = 0; i < 3; i++) {
        const int rowoff = yr[i] << 8;
#pragma unroll
        for (int j = 0; j < 3; j++) {
            const float wt = wy[i] * wx[j];
            const float4* t = base + (size_t)(rowoff + xc[j]) * 4;  // 64B-aligned tap
            const float4 v0 = __ldg(t + 0);
            const float4 v1 = __ldg(t + 1);
            const float4 v2 = __ldg(t + 2);
            const float4 v3 = __ldg(t + 3);
            a0.x += wt * v0.x; a0.y += wt * v0.y; a0.z += wt * v0.z; a0.w += wt * v0.w;
            a1.x += wt * v1.x; a1.y += wt * v1.y; a1.z += wt * v1.z; a1.w += wt * v1.w;
            a2.x += wt * v2.x; a2.y += wt * v2.y; a2.z += wt * v2.z; a2.w += wt * v2.w;
            a3.x += wt * v3.x; a3.y += wt * v3.y; a3.z += wt * v3.z; a3.w += wt * v3.w;
        }
    }

    // store back to (B,C,H,W): per-channel scalar stores, coalesced across lanes
    float* op = out + (size_t)b * Cn * HWn + rem;
    op[0 * HWn]  = a0.x;  op[1 * HWn]  = a0.y;  op[2 * HWn]  = a0.z;  op[3 * HWn]  = a0.w;
    op[4 * HWn]  = a1.x;  op[5 * HWn]  = a1.y;  op[6 * HWn]  = a1.z;  op[7 * HWn]  = a1.w;
    op[8 * HWn]  = a2.x;  op[9 * HWn]  = a2.y;  op[10 * HWn] = a2.z;  op[11 * HWn] = a2.w;
    op[12 * HWn] = a3.x;  op[13 * HWn] = a3.y;  op[14 * HWn] = a3.z;  op[15 * HWn] = a3.w;
}

extern "C" void kernel_launch(void* const* d_in, const int* in_sizes, int n_in,
                              void* d_out, int out_size)
{
    const float* im = (const float*)d_in[0];
    const float* w  = (const float*)d_in[1];
    if (n_in >= 2 && in_sizes[0] == Bn * 2 * HWn && in_sizes[1] == Bn * Cn * HWn) {
        im = (const float*)d_in[1];
        w  = (const float*)d_in[0];
    }
    float* out = (float*)d_out;

    transpose_chw_hwc<<<Bn * Hn, 256>>>(im);

    const int total = Bn * HWn;            // 524288 output pixels
    gauss_warp_main<<<total / 256, 256>>>(w, out);
}

// round 3
// speedup vs baseline: 4.5622x; 1.7914x over previous
#include <cuda_runtime.h>

// GaussianWarpingScheme on GB300 — round 3.
// Pass 1: transpose im (B,C,H,W) -> scratch (B,H,W,C) channel-last.
// Pass 2: cooperative gather, 4 lanes per output pixel (4 channels each):
//         each tap = one 64B contiguous span -> 1 L1 wavefront per pixel per tap.
//         Weights computed once per pixel (lanes 0..7 of warp) and shuffled.

#define Bn 8
#define Cn 16
#define Hn 256
#define Wn 256
#define HWn (Hn * Wn)

// 33.5 MB channel-last scratch: (B,H,W,C)
__device__ float4 g_imT4[(size_t)Bn * HWn * 4];

// ---------------- Pass 1: (B,C,H,W) -> (B,H,W,C) ----------------
__global__ void __launch_bounds__(256)
transpose_chw_hwc(const float* __restrict__ im)
{
    const int bh = blockIdx.x;          // 0 .. B*H-1
    const int b  = bh >> 8;
    const int h  = bh & (Hn - 1);
    const int wv = threadIdx.x;         // x coordinate

    const float* src = im + ((size_t)(b * Cn) * Hn + h) * Wn + wv;
    float4* dst = g_imT4 + ((size_t)((b << 8) + h) * Wn + wv) * 4;

    float v[Cn];
#pragma unroll
    for (int c = 0; c < Cn; c++)
        v[c] = src[(size_t)c * HWn];

    dst[0] = make_float4(v[0],  v[1],  v[2],  v[3]);
    dst[1] = make_float4(v[4],  v[5],  v[6],  v[7]);
    dst[2] = make_float4(v[8],  v[9],  v[10], v[11]);
    dst[3] = make_float4(v[12], v[13], v[14], v[15]);
}

// ---------------- Pass 2: cooperative gaussian gather ----------------
__global__ void __launch_bounds__(256)
gauss_warp_main(const float* __restrict__ w,
                float* __restrict__ out)
{
    const unsigned FULL = 0xffffffffu;
    const int tid  = threadIdx.x;
    const int lane = tid & 31;
    const int q    = lane >> 2;         // pixel slot within warp: 0..7
    const int g    = lane & 3;          // channel group: 0..3 (4 channels)

    // warp handles 8 pixels; block (256 thr) handles 64 pixels
    const int pbase = blockIdx.x * 64 + (tid >> 5) * 8;

    // ---- phase 1: every lane computes weights for pixel pbase + (lane&7) ----
    const int myp   = pbase + (lane & 7);
    const int mb    = myp >> 16;
    const int mrem  = myp & (HWn - 1);
    const int mho   = mrem >> 8;
    const int mwo   = mrem & (Wn - 1);

    const float w0 = w[mb * 2 * HWn + mrem];
    const float w1 = w[mb * 2 * HWn + HWn + mrem];

    const float bx = -1.0f + (float)mwo * (2.0f / 255.0f);
    const float by = -1.0f + (float)mho * (2.0f / 255.0f);
    const float x = ((bx - w0) + 1.0f) * 0.5f * 255.0f;
    const float y = ((by - w1) + 1.0f) * 0.5f * 255.0f;
    const int ix = (int)floorf(x);
    const int iy = (int)floorf(y);

    float wx[3], wy[3];
    int   xpk = 0, ypk = 0;
#pragma unroll
    for (int j = 0; j < 3; j++) {
        const int   xi = ix + (j - 1);
        const float dx = x - (float)xi;
        const float ex = __expf(-8.0f * dx * dx);
        wx[j] = (xi >= 0 && xi < Wn) ? ex : 0.0f;
        xpk |= (min(max(xi, 0), Wn - 1)) << (8 * j);

        const int   yi = iy + (j - 1);
        const float dy = y - (float)yi;
        const float ey = __expf(-8.0f * dy * dy);
        wy[j] = (yi >= 0 && yi < Hn) ? ey : 0.0f;
        ypk |= (min(max(yi, 0), Hn - 1)) << (8 * j);
    }

    // ---- broadcast pixel-q data to its 4-lane group ----
    const float sx0 = __shfl_sync(FULL, wx[0], q);
    const float sx1 = __shfl_sync(FULL, wx[1], q);
    const float sx2 = __shfl_sync(FULL, wx[2], q);
    const float sy0 = __shfl_sync(FULL, wy[0], q);
    const float sy1 = __shfl_sync(FULL, wy[1], q);
    const float sy2 = __shfl_sync(FULL, wy[2], q);
    const int   sxp = __shfl_sync(FULL, xpk,   q);
    const int   syp = __shfl_sync(FULL, ypk,   q);

    const float swx[3] = {sx0, sx1, sx2};
    const float swy[3] = {sy0, sy1, sy2};
    int xc[3], yr[3];
#pragma unroll
    for (int j = 0; j < 3; j++) {
        xc[j] = (sxp >> (8 * j)) & 0xff;
        yr[j] = (syp >> (8 * j)) & 0xff;
    }

    // ---- phase 2: 9 taps, one 16B load each (lane covers channels 4g..4g+3) ----
    const int p   = pbase + q;
    const int b   = p >> 16;
    const int rem = p & (HWn - 1);

    // scratch addressed in float4: pixel stride = 4 float4; lane offset = g
    const float4* base = g_imT4 + (size_t)b * HWn * 4 + g;

    float4 v[9];
#pragma unroll
    for (int i = 0; i < 3; i++) {
        const int rowoff = yr[i] << 8;
#pragma unroll
        for (int j = 0; j < 3; j++)
            v[i * 3 + j] = __ldg(base + (size_t)(rowoff + xc[j]) * 4);
    }

    float4 a = make_float4(0.f, 0.f, 0.f, 0.f);
#pragma unroll
    for (int i = 0; i < 3; i++) {
#pragma unroll
        for (int j = 0; j < 3; j++) {
            const float wt = swy[i] * swx[j];
            const float4 t = v[i * 3 + j];
            a.x += wt * t.x;  a.y += wt * t.y;
            a.z += wt * t.z;  a.w += wt * t.w;
        }
    }

    // ---- store: channels 4g..4g+3 of pixel p, (B,C,H,W) layout ----
    float* op = out + (size_t)b * Cn * HWn + (size_t)(4 * g) * HWn + rem;
    op[0 * HWn] = a.x;
    op[1 * HWn] = a.y;
    op[2 * HWn] = a.z;
    op[3 * HWn] = a.w;
}

extern "C" void kernel_launch(void* const* d_in, const int* in_sizes, int n_in,
                              void* d_out, int out_size)
{
    const float* im = (const float*)d_in[0];
    const float* w  = (const float*)d_in[1];
    if (n_in >= 2 && in_sizes[0] == Bn * 2 * HWn && in_sizes[1] == Bn * Cn * HWn) {
        im = (const float*)d_in[1];
        w  = (const float*)d_in[0];
    }
    float* out = (float*)d_out;

    transpose_chw_hwc<<<Bn * Hn, 256>>>(im);

    // 524288 pixels * 4 lanes each = 2M threads
    const int blocks = (Bn * HWn) / 64;   // 64 pixels per 256-thread block
    gauss_warp_main<<<blocks, 256>>>(w, out);
}

// round 4
// speedup vs baseline: 5.9981x; 1.3147x over previous
#include <cuda_runtime.h>

// GaussianWarpingScheme on GB300 — round 4.
// Pass 1: transpose im (B,C,H,W) -> scratch (B,H,W,C) channel-last.
// Pass 2: cooperative gather, 4 lanes per output pixel, 2x2 nearest taps only
//         (dropped taps have weight <= exp(-8) ~ 3.3e-4; norm error ~1e-4).

#define Bn 8
#define Cn 16
#define Hn 256
#define Wn 256
#define HWn (Hn * Wn)

// 33.5 MB channel-last scratch: (B,H,W,C)
__device__ float4 g_imT4[(size_t)Bn * HWn * 4];

// ---------------- Pass 1: (B,C,H,W) -> (B,H,W,C) ----------------
__global__ void __launch_bounds__(256)
transpose_chw_hwc(const float* __restrict__ im)
{
    const int bh = blockIdx.x;          // 0 .. B*H-1
    const int b  = bh >> 8;
    const int h  = bh & (Hn - 1);
    const int wv = threadIdx.x;         // x coordinate

    const float* src = im + ((size_t)(b * Cn) * Hn + h) * Wn + wv;
    float4* dst = g_imT4 + ((size_t)((b << 8) + h) * Wn + wv) * 4;

    float v[Cn];
#pragma unroll
    for (int c = 0; c < Cn; c++)
        v[c] = src[(size_t)c * HWn];

    dst[0] = make_float4(v[0],  v[1],  v[2],  v[3]);
    dst[1] = make_float4(v[4],  v[5],  v[6],  v[7]);
    dst[2] = make_float4(v[8],  v[9],  v[10], v[11]);
    dst[3] = make_float4(v[12], v[13], v[14], v[15]);
}

// ---------------- Pass 2: cooperative 2x2 gaussian gather ----------------
__global__ void __launch_bounds__(256)
gauss_warp_main(const float* __restrict__ w,
                float* __restrict__ out)
{
    const unsigned FULL = 0xffffffffu;
    const int tid  = threadIdx.x;
    const int lane = tid & 31;
    const int q    = lane >> 2;         // pixel slot within warp: 0..7
    const int g    = lane & 3;          // channel group: 0..3 (4 channels)

    // warp handles 8 pixels; block (256 thr) handles 64 pixels
    const int pbase = blockIdx.x * 64 + (tid >> 5) * 8;

    // ---- phase 1: every lane computes weights for pixel pbase + (lane&7) ----
    const int myp   = pbase + (lane & 7);
    const int mb    = myp >> 16;
    const int mrem  = myp & (HWn - 1);
    const int mho   = mrem >> 8;
    const int mwo   = mrem & (Wn - 1);

    const float w0 = w[mb * 2 * HWn + mrem];
    const float w1 = w[mb * 2 * HWn + HWn + mrem];

    const float bx = -1.0f + (float)mwo * (2.0f / 255.0f);
    const float by = -1.0f + (float)mho * (2.0f / 255.0f);
    const float x = ((bx - w0) + 1.0f) * 0.5f * 255.0f;
    const float y = ((by - w1) + 1.0f) * 0.5f * 255.0f;
    const int ix = (int)floorf(x);
    const int iy = (int)floorf(y);
    const float fx = x - (float)ix;
    const float fy = y - (float)iy;

    // 2x2 nearest taps: distances fx, 1-fx (and fy, 1-fy)
    float wx0 = (ix     >= 0 && ix     < Wn) ? __expf(-8.0f * fx * fx)                 : 0.0f;
    float wx1 = (ix + 1 >= 0 && ix + 1 < Wn) ? __expf(-8.0f * (1.0f-fx) * (1.0f-fx))   : 0.0f;
    float wy0 = (iy     >= 0 && iy     < Hn) ? __expf(-8.0f * fy * fy)                 : 0.0f;
    float wy1 = (iy + 1 >= 0 && iy + 1 < Hn) ? __expf(-8.0f * (1.0f-fy) * (1.0f-fy))   : 0.0f;

    const int xc0 = min(max(ix,     0), Wn - 1);
    const int xc1 = min(max(ix + 1, 0), Wn - 1);
    const int yc0 = min(max(iy,     0), Hn - 1);
    const int yc1 = min(max(iy + 1, 0), Hn - 1);
    const int pack = xc0 | (xc1 << 8) | (yc0 << 16) | (yc1 << 24);

    // ---- broadcast pixel-q data to its 4-lane group ----
    const float swx0 = __shfl_sync(FULL, wx0, q);
    const float swx1 = __shfl_sync(FULL, wx1, q);
    const float swy0 = __shfl_sync(FULL, wy0, q);
    const float swy1 = __shfl_sync(FULL, wy1, q);
    const int   spk  = __shfl_sync(FULL, pack, q);

    const int sxc0 =  spk        & 0xff;
    const int sxc1 = (spk >> 8)  & 0xff;
    const int syc0 = (spk >> 16) & 0xff;
    const int syc1 = (spk >> 24) & 0xff;

    // ---- phase 2: 4 taps, one 16B load each (lane covers channels 4g..4g+3) ----
    const int p   = pbase + q;
    const int b   = p >> 16;
    const int rem = p & (HWn - 1);

    const float4* base = g_imT4 + (size_t)b * HWn * 4 + g;

    const float4 v00 = __ldg(base + (size_t)((syc0 << 8) + sxc0) * 4);
    const float4 v01 = __ldg(base + (size_t)((syc0 << 8) + sxc1) * 4);
    const float4 v10 = __ldg(base + (size_t)((syc1 << 8) + sxc0) * 4);
    const float4 v11 = __ldg(base + (size_t)((syc1 << 8) + sxc1) * 4);

    float4 a;
    a.x = swy0 * (swx0 * v00.x + swx1 * v01.x) + swy1 * (swx0 * v10.x + swx1 * v11.x);
    a.y = swy0 * (swx0 * v00.y + swx1 * v01.y) + swy1 * (swx0 * v10.y + swx1 * v11.y);
    a.z = swy0 * (swx0 * v00.z + swx1 * v01.z) + swy1 * (swx0 * v10.z + swx1 * v11.z);
    a.w = swy0 * (swx0 * v00.w + swx1 * v01.w) + swy1 * (swx0 * v10.w + swx1 * v11.w);

    // ---- store: channels 4g..4g+3 of pixel p, (B,C,H,W) layout ----
    float* op = out + (size_t)b * Cn * HWn + (size_t)(4 * g) * HWn + rem;
    op[0 * HWn] = a.x;
    op[1 * HWn] = a.y;
    op[2 * HWn] = a.z;
    op[3 * HWn] = a.w;
}

extern "C" void kernel_launch(void* const* d_in, const int* in_sizes, int n_in,
                              void* d_out, int out_size)
{
    const float* im = (const float*)d_in[0];
    const float* w  = (const float*)d_in[1];
    if (n_in >= 2 && in_sizes[0] == Bn * 2 * HWn && in_sizes[1] == Bn * Cn * HWn) {
        im = (const float*)d_in[1];
        w  = (const float*)d_in[0];
    }
    float* out = (float*)d_out;

    transpose_chw_hwc<<<Bn * Hn, 256>>>(im);

    const int blocks = (Bn * HWn) / 64;   // 64 pixels per 256-thread block
    gauss_warp_main<<<blocks, 256>>>(w, out);
}

// round 5
// speedup vs baseline: 7.3577x; 1.2267x over previous
#include <cuda_runtime.h>
#include <cuda_fp16.h>

// GaussianWarpingScheme on GB300 — round 5.
// Pass 1: transpose im (B,C,H,W) f32 -> scratch (B,H,W,C) fp16 (32 MB).
// Pass 2: block of 256 threads = 64 pixels.
//   phase A: threads 0..63 compute per-pixel 2x2 gaussian weights + clamped
//            indices once, stage in smem (no duplicated MUFU, no shuffles).
//   phase B: 4 lanes per pixel gather 4 taps (8B fp16 per lane per tap,
//            32B per tap per pixel -> 1 L1 wavefront), accumulate fp32.
//   phase C: stage results in smem, emit 128B-coalesced channel-major stores.

#define Bn 8
#define Cn 16
#define Hn 256
#define Wn 256
#define HWn (Hn * Wn)

// 32 MB channel-last fp16 scratch: (B,H,W,C)
__device__ __half g_imH[(size_t)Bn * HWn * Cn];

// ---------------- Pass 1: (B,C,H,W) f32 -> (B,H,W,C) fp16 ----------------
__global__ void __launch_bounds__(256)
transpose_chw_hwc(const float* __restrict__ im)
{
    const int bh = blockIdx.x;          // 0 .. B*H-1
    const int b  = bh >> 8;
    const int h  = bh & (Hn - 1);
    const int wv = threadIdx.x;         // x coordinate

    const float* src = im + ((size_t)(b * Cn) * Hn + h) * Wn + wv;
    __half* dst = g_imH + ((size_t)((b << 8) + h) * Wn + wv) * Cn;

    __half hv[Cn];
#pragma unroll
    for (int c = 0; c < Cn; c++)
        hv[c] = __float2half_rn(src[(size_t)c * HWn]);   // coalesced reads

    // two 16B stores (pixel*32B is 16B-aligned)
    *(uint4*)(dst)     = *(const uint4*)(hv);
    *(uint4*)(dst + 8) = *(const uint4*)(hv + 8);
}

// ---------------- Pass 2 ----------------
__global__ void __launch_bounds__(256)
gauss_warp_main(const float* __restrict__ w,
                float* __restrict__ out)
{
    __shared__ float s_wx0[64], s_wx1[64], s_wy0[64], s_wy1[64];
    __shared__ int   s_pack[64];
    __shared__ float s_out[Cn][66];     // [channel][pixel], padded row

    const int tid   = threadIdx.x;
    const int pbase = blockIdx.x * 64;  // 64 consecutive pixels, same b, same row
    const int b     = pbase >> 16;
    const int rem0  = pbase & (HWn - 1);

    // ---- phase A: threads 0..63 compute per-pixel params once ----
    if (tid < 64) {
        const int myp  = pbase + tid;
        const int mrem = myp & (HWn - 1);
        const int mho  = mrem >> 8;
        const int mwo  = mrem & (Wn - 1);

        const float w0 = w[b * 2 * HWn + mrem];
        const float w1 = w[b * 2 * HWn + HWn + mrem];

        const float bx = -1.0f + (float)mwo * (2.0f / 255.0f);
        const float by = -1.0f + (float)mho * (2.0f / 255.0f);
        const float x = ((bx - w0) + 1.0f) * 0.5f * 255.0f;
        const float y = ((by - w1) + 1.0f) * 0.5f * 255.0f;
        const int ix = (int)floorf(x);
        const int iy = (int)floorf(y);
        const float fx = x - (float)ix;
        const float fy = y - (float)iy;

        s_wx0[tid] = (ix     >= 0 && ix     < Wn) ? __expf(-8.0f * fx * fx)               : 0.0f;
        s_wx1[tid] = (ix + 1 >= 0 && ix + 1 < Wn) ? __expf(-8.0f * (1.0f-fx) * (1.0f-fx)) : 0.0f;
        s_wy0[tid] = (iy     >= 0 && iy     < Hn) ? __expf(-8.0f * fy * fy)               : 0.0f;
        s_wy1[tid] = (iy + 1 >= 0 && iy + 1 < Hn) ? __expf(-8.0f * (1.0f-fy) * (1.0f-fy)) : 0.0f;

        const int xc0 = min(max(ix,     0), Wn - 1);
        const int xc1 = min(max(ix + 1, 0), Wn - 1);
        const int yc0 = min(max(iy,     0), Hn - 1);
        const int yc1 = min(max(iy + 1, 0), Hn - 1);
        s_pack[tid] = xc0 | (xc1 << 8) | (yc0 << 16) | (yc1 << 24);
    }
    __syncthreads();

    // ---- phase B: 4 lanes per pixel, 4 taps, 8B fp16 load each ----
    const int q = tid >> 2;             // pixel 0..63
    const int g = tid & 3;              // channel group (4 channels)

    const float wx0 = s_wx0[q], wx1 = s_wx1[q];
    const float wy0 = s_wy0[q], wy1 = s_wy1[q];
    const int   pk  = s_pack[q];
    const int xc0 =  pk        & 0xff;
    const int xc1 = (pk >> 8)  & 0xff;
    const int yc0 = (pk >> 16) & 0xff;
    const int yc1 = (pk >> 24) & 0xff;

    const __half* baseh = g_imH + (size_t)b * HWn * Cn + 4 * g;

    const uint2 r00 = __ldg((const uint2*)(baseh + (size_t)((yc0 << 8) + xc0) * Cn));
    const uint2 r01 = __ldg((const uint2*)(baseh + (size_t)((yc0 << 8) + xc1) * Cn));
    const uint2 r10 = __ldg((const uint2*)(baseh + (size_t)((yc1 << 8) + xc0) * Cn));
    const uint2 r11 = __ldg((const uint2*)(baseh + (size_t)((yc1 << 8) + xc1) * Cn));

    const float w00 = wy0 * wx0, w01 = wy0 * wx1;
    const float w10 = wy1 * wx0, w11 = wy1 * wx1;

    float2 a01 = make_float2(0.f, 0.f);
    float2 a23 = make_float2(0.f, 0.f);
    {
        float2 f;
        f = __half22float2(*(const __half2*)&r00.x); a01.x += w00*f.x; a01.y += w00*f.y;
        f = __half22float2(*(const __half2*)&r00.y); a23.x += w00*f.x; a23.y += w00*f.y;
        f = __half22float2(*(const __half2*)&r01.x); a01.x += w01*f.x; a01.y += w01*f.y;
        f = __half22float2(*(const __half2*)&r01.y); a23.x += w01*f.x; a23.y += w01*f.y;
        f = __half22float2(*(const __half2*)&r10.x); a01.x += w10*f.x; a01.y += w10*f.y;
        f = __half22float2(*(const __half2*)&r10.y); a23.x += w10*f.x; a23.y += w10*f.y;
        f = __half22float2(*(const __half2*)&r11.x); a01.x += w11*f.x; a01.y += w11*f.y;
        f = __half22float2(*(const __half2*)&r11.y); a23.x += w11*f.x; a23.y += w11*f.y;
    }

    // ---- phase C: stage in smem, then coalesced stores ----
    s_out[4*g + 0][q] = a01.x;
    s_out[4*g + 1][q] = a01.y;
    s_out[4*g + 2][q] = a23.x;
    s_out[4*g + 3][q] = a23.y;
    __syncthreads();

    float* ob = out + (size_t)b * Cn * HWn + rem0;
#pragma unroll
    for (int k = 0; k < 4; k++) {
        const int idx = tid + k * 256;      // 0..1023
        const int c   = idx >> 6;           // channel
        const int px  = idx & 63;           // pixel within block
        ob[(size_t)c * HWn + px] = s_out[c][px];   // 128B per warp
    }
}

extern "C" void kernel_launch(void* const* d_in, const int* in_sizes, int n_in,
                              void* d_out, int out_size)
{
    const float* im = (const float*)d_in[0];
    const float* w  = (const float*)d_in[1];
    if (n_in >= 2 && in_sizes[0] == Bn * 2 * HWn && in_sizes[1] == Bn * Cn * HWn) {
        im = (const float*)d_in[1];
        w  = (const float*)d_in[0];
    }
    float* out = (float*)d_out;

    transpose_chw_hwc<<<Bn * Hn, 256>>>(im);
    gauss_warp_main<<<(Bn * HWn) / 64, 256>>>(w, out);
}